// round 15
// baseline (speedup 1.0000x reference)
#include <cuda_runtime.h>
#include <cuda_bf16.h>
#include <cuda_fp16.h>
#include <cstdint>

#define BATCH 8
#define DM 256
#define NH 4
#define HD 64
#define SEQ 2048
#define BH (BATCH*NH)

typedef unsigned short u16;

// Q: [bh][n][d] fp16 hi/lo (pre-scaled by 0.125*log2e) ; K: [bh][m][d] fp16 ; V: [bh][d][m] fp16
__device__ u16  g_qh[(size_t)BH*SEQ*HD];
__device__ u16  g_ql[(size_t)BH*SEQ*HD];
__device__ u16  g_kh[(size_t)BH*SEQ*HD];
__device__ u16  g_vh[(size_t)BH*HD*SEQ];
__device__ float g_x [(size_t)BATCH*DM*SEQ];
// pre-split weights: [mat][o][i] fp16 hi/lo
__device__ u16  g_wh[4*DM*DM];
__device__ u16  g_wl[4*DM*DM];

#define QSCALE 0.18033688011112042f   // 0.125 * log2(e)

__device__ __forceinline__ float ex2f(float x) {
    float r; asm("ex2.approx.f32 %0, %1;" : "=f"(r) : "f"(x)); return r;
}
__device__ __forceinline__ uint32_t packh2(float lo, float hi) {
    uint32_t r; asm("cvt.rn.f16x2.f32 %0, %1, %2;" : "=r"(r) : "f"(hi), "f"(lo)); return r;
}
__device__ __forceinline__ void splithalf(float v, u16& h, u16& l) {
    __half hb = __float2half_rn(v);
    __half lb = __float2half_rn(v - __half2float(hb));
    h = __half_as_ushort(hb); l = __half_as_ushort(lb);
}
__device__ __forceinline__ void mma16816h(float* d, const uint32_t* a, uint32_t b0, uint32_t b1) {
    asm volatile("mma.sync.aligned.m16n8k16.row.col.f32.f16.f16.f32 "
                 "{%0,%1,%2,%3}, {%4,%5,%6,%7}, {%8,%9}, {%0,%1,%2,%3};\n"
                 : "+f"(d[0]), "+f"(d[1]), "+f"(d[2]), "+f"(d[3])
                 : "r"(a[0]), "r"(a[1]), "r"(a[2]), "r"(a[3]), "r"(b0), "r"(b1));
}
__device__ __forceinline__ void ldsm4(uint32_t a, uint32_t& r0, uint32_t& r1,
                                      uint32_t& r2, uint32_t& r3) {
    asm volatile("ldmatrix.sync.aligned.m8n8.x4.shared.b16 {%0,%1,%2,%3}, [%4];"
                 : "=r"(r0), "=r"(r1), "=r"(r2), "=r"(r3) : "r"(a));
}
__device__ __forceinline__ void ldsm4t(uint32_t a, uint32_t& r0, uint32_t& r1,
                                       uint32_t& r2, uint32_t& r3) {
    asm volatile("ldmatrix.sync.aligned.m8n8.x4.trans.shared.b16 {%0,%1,%2,%3}, [%4];"
                 : "=r"(r0), "=r"(r1), "=r"(r2), "=r"(r3) : "r"(a));
}
__device__ __forceinline__ void cp16(uint32_t saddr, const void* g) {
    asm volatile("cp.async.ca.shared.global [%0], [%1], 16;" :: "r"(saddr), "l"(g));
}
#define CP_COMMIT() asm volatile("cp.async.commit_group;" ::: "memory")
#define CP_WAIT(n)  asm volatile("cp.async.wait_group %0;" :: "n"(n) : "memory")

// ---------------------------------------------------------------------------
// One-shot weight splitter: 4 x [256][256] fp32 -> fp16 hi/lo. Grid (32, 4).
// ---------------------------------------------------------------------------
__global__ __launch_bounds__(256)
void wsplit_kernel(const float* __restrict__ W0, const float* __restrict__ W1,
                   const float* __restrict__ W2, const float* __restrict__ W3,
                   u16* __restrict__ Wh, u16* __restrict__ Wl) {
    const int mat = blockIdx.y;
    const float* src = (mat == 0) ? W0 : (mat == 1) ? W1 : (mat == 2) ? W2 : W3;
    const size_t base = (size_t)mat * DM * DM;
    const int i0 = (blockIdx.x * 256 + threadIdx.x) * 8;
    u16 h8[8], l8[8];
    #pragma unroll
    for (int p = 0; p < 8; p++)
        splithalf(src[i0 + p], h8[p], l8[p]);
    *(uint4*)&Wh[base + i0] = *(uint4*)h8;
    *(uint4*)&Wl[base + i0] = *(uint4*)l8;
}

// ---------------------------------------------------------------------------
// Tensor-core projection v6: fp16 2-term W (pre-split), X fp16 hi.
// Tile 128o x 128n (256 CTAs = one wave at 2 CTAs/SM). K chunks of 64:
// 4 chunks, W via cp.async 1-ahead (2 stages), X LDG 1-ahead in registers.
// 64 MMAs/warp/chunk cover the staging latency; 8 barriers total.
// MODE 0: fp32 [b][o][n]; MODE 1: fp16 hi/lo [bh][n][d], pre-scaled (Q);
// MODE 3: fp16 hi [bh][n][d] (K); MODE 2: fp16 hi [bh][d][m] (V).
// Grid (SEQ/128, DM/128, BATCH). 256 threads.
// ---------------------------------------------------------------------------
#define PJ_W 18432                 // 128 rows x 144B (one of hi/lo)
#define PJ_X 17408                 // 64 rows x 272B (fp16 hi only)
#define PJSTG (2*PJ_W + PJ_X)      // 54272 per stage
#define PJ_WH(s) ((s)*PJSTG)
#define PJ_WL(s) ((s)*PJSTG + PJ_W)
#define PJ_XH(s) ((s)*PJSTG + 2*PJ_W)
#define PSM_BYTES (2*PJSTG)        // 108544

template<int MODE>
__global__ __launch_bounds__(256, 2)
void proj_tc(const u16* __restrict__ Wh, const u16* __restrict__ Wl,
             const float* __restrict__ bias,
             const float* __restrict__ X, float* __restrict__ C0,
             u16* __restrict__ Ch, u16* __restrict__ Cl) {
    extern __shared__ __align__(16) char psm[];
    __shared__ float biasSm[128];
    const uint32_t sbase = (uint32_t)__cvta_generic_to_shared(psm);
    const int n0 = blockIdx.x * 128, o0 = blockIdx.y * 128, b = blockIdx.z;
    const int tid = threadIdx.x;
    const int w = tid >> 5, l = tid & 31;
    const int g = l >> 2, tt = l & 3;
    if (tid < 128) biasSm[tid] = bias[o0 + tid];

    float O[16][4];
    #pragma unroll
    for (int i = 0; i < 16; i++) { O[i][0]=0.f; O[i][1]=0.f; O[i][2]=0.f; O[i][3]=0.f; }

    const uint32_t xoff = (uint32_t)((8*((l >> 3) & 1) + (l & 7)) * 272 + 16 * (l >> 4));
    const int wrow = tid >> 1, wpc = tid & 1;        // W: 2 threads/row, 64B each
    const int xrow = tid >> 2, xn32 = (tid & 3) * 32;

    const u16* wsH = Wh + (size_t)(o0 + wrow) * DM + wpc * 32;
    const u16* wsL = Wl + (size_t)(o0 + wrow) * DM + wpc * 32;
    const float* xsrc = X + ((size_t)b * DM + xrow) * SEQ + n0 + xn32;
    const uint32_t wdh = sbase + wrow * 144 + wpc * 64;

    float4 rx[8];

    #define PJ_WCP(c, s) do { \
        _Pragma("unroll") \
        for (int u = 0; u < 4; u++) { \
            cp16(wdh + PJ_WH(s) + 16*u, wsH + (c)*64 + 8*u); \
            cp16(wdh + PJ_WL(s) + 16*u, wsL + (c)*64 + 8*u); \
        } \
        CP_COMMIT(); \
    } while (0)
    #define PJ_XFETCH(c) do { \
        const float* xp_ = xsrc + (size_t)((c)*64) * SEQ; \
        _Pragma("unroll") \
        for (int u = 0; u < 8; u++) rx[u] = *(const float4*)(xp_ + 4*u); \
    } while (0)
    #define PJ_XSTORE(s) do { \
        char* xd_ = psm + PJ_XH(s) + xrow*272 + xn32*2; \
        _Pragma("unroll") \
        for (int u = 0; u < 4; u++) { \
            uint32_t a0 = packh2(rx[2*u].x, rx[2*u].y); \
            uint32_t a1 = packh2(rx[2*u].z, rx[2*u].w); \
            uint32_t a2 = packh2(rx[2*u+1].x, rx[2*u+1].y); \
            uint32_t a3 = packh2(rx[2*u+1].z, rx[2*u+1].w); \
            *(uint4*)(xd_ + 16*u) = make_uint4(a0, a1, a2, a3); \
        } \
    } while (0)

    // prologue: chunk 0 into stage 0
    PJ_WCP(0, 0);
    PJ_XFETCH(0);
    PJ_XSTORE(0);
    CP_WAIT(0);
    __syncthreads();

    for (int c = 0; c < 4; c++) {
        const int cur = c & 1;
        if (c < 3) { PJ_WCP(c + 1, 1 - cur); PJ_XFETCH(c + 1); }
        // ---- compute chunk c: 4 k16 slabs
        #pragma unroll
        for (int s = 0; s < 4; s++) {
            uint32_t ah[4], al[4];
            const char* wp = psm + PJ_WH(cur) + (w*16 + g)*144 + s*32 + tt*4;
            ah[0] = *(const uint32_t*)wp;
            ah[1] = *(const uint32_t*)(wp + 8*144);
            ah[2] = *(const uint32_t*)(wp + 16);
            ah[3] = *(const uint32_t*)(wp + 8*144 + 16);
            const char* wq = wp + PJ_W;
            al[0] = *(const uint32_t*)wq;
            al[1] = *(const uint32_t*)(wq + 8*144);
            al[2] = *(const uint32_t*)(wq + 16);
            al[3] = *(const uint32_t*)(wq + 8*144 + 16);
            const uint32_t xb = sbase + PJ_XH(cur) + s*4352 + xoff;
            #pragma unroll
            for (int nbp = 0; nbp < 8; nbp++) {
                uint32_t h0, h1, h2, h3;
                ldsm4t(xb + 32*nbp, h0, h1, h2, h3);
                mma16816h(O[2*nbp],   ah, h0, h1);
                mma16816h(O[2*nbp+1], ah, h2, h3);
                mma16816h(O[2*nbp],   al, h0, h1);
                mma16816h(O[2*nbp+1], al, h2, h3);
            }
        }
        if (c < 3) { PJ_XSTORE(1 - cur); CP_WAIT(0); }
        __syncthreads();
    }
    #undef PJ_WCP
    #undef PJ_XFETCH
    #undef PJ_XSTORE

    // ---- epilogue: O -> smem [128 o][136 pitch] fp32 (reuses stage area)
    float* Osm = (float*)psm;
    {
        const int r = w*16 + g;
        #pragma unroll
        for (int nb = 0; nb < 16; nb++) {
            const int cc = nb*8 + 2*tt;
            Osm[r*136 + cc]         = O[nb][0];
            Osm[r*136 + cc + 1]     = O[nb][1];
            Osm[(r+8)*136 + cc]     = O[nb][2];
            Osm[(r+8)*136 + cc + 1] = O[nb][3];
        }
    }
    __syncthreads();

    if (MODE == 0) {
        const int o = tid >> 1, half = (tid & 1) * 64;
        const float bi = biasSm[o];
        const float* src = Osm + o*136 + half;
        float* dst = C0 + ((size_t)b * DM + o0 + o) * SEQ + n0 + half;
        #pragma unroll
        for (int j = 0; j < 16; j++) {
            float4 v = *(const float4*)(src + 4*j);
            v.x += bi; v.y += bi; v.z += bi; v.w += bi;
            *(float4*)(dst + 4*j) = v;
        }
    } else if (MODE == 1) {
        #pragma unroll
        for (int r = 0; r < 2; r++) {
            const int task = tid + 256*r;
            const int n = task >> 2, hh = task & 3;
            u16 oh[32], ol[32];
            #pragma unroll
            for (int d = 0; d < 32; d++)
                splithalf((Osm[(4*d + hh)*136 + n] + biasSm[4*d + hh]) * QSCALE, oh[d], ol[d]);
            size_t dst = ((size_t)(b*NH + hh) * SEQ + n0 + n) * HD + (o0 >> 2);
            #pragma unroll
            for (int j = 0; j < 4; j++) {
                *(uint4*)(Ch + dst + 8*j) = *(uint4*)(oh + 8*j);
                *(uint4*)(Cl + dst + 8*j) = *(uint4*)(ol + 8*j);
            }
        }
    } else if (MODE == 3) {
        #pragma unroll
        for (int r = 0; r < 2; r++) {
            const int task = tid + 256*r;
            const int n = task >> 2, hh = task & 3;
            u16 oh[32];
            #pragma unroll
            for (int d = 0; d < 32; d++)
                oh[d] = __half_as_ushort(__float2half_rn(Osm[(4*d + hh)*136 + n] + biasSm[4*d + hh]));
            size_t dst = ((size_t)(b*NH + hh) * SEQ + n0 + n) * HD + (o0 >> 2);
            #pragma unroll
            for (int j = 0; j < 4; j++)
                *(uint4*)(Ch + dst + 8*j) = *(uint4*)(oh + 8*j);
        }
    } else {
        const int o = tid >> 1, mh = (tid & 1) * 64;
        const int chn = o0 + o;
        const int d = chn >> 2, hh = chn & 3;
        const float bi = biasSm[o];
        const float* src = Osm + o*136 + mh;
        u16 xh[64];
        #pragma unroll
        for (int j = 0; j < 64; j++)
            xh[j] = __half_as_ushort(__float2half_rn(src[j] + bi));
        size_t dst = ((size_t)(b*NH + hh) * HD + d) * SEQ + n0 + mh;
        #pragma unroll
        for (int j = 0; j < 8; j++)
            *(uint4*)(Ch + dst + 8*j) = *(uint4*)(xh + 8*j);
    }
}

// ---------------------------------------------------------------------------
// Fused flash attention (R9/R13 best, f32-accum both S terms): fp16, Q 2-term
// (pre-scaled), K/V/P single-term, ls via all-ones MMA. Double-buffered
// cp.async. 2 CTAs/SM. 256 threads. Grid (SEQ/128, BH). smem 106KB.
// ---------------------------------------------------------------------------
#define KPITCH 144
#define VPITCH 272
#define STG 35840
#define QOFF 71680
#define FLASH_SMEM 108544

__global__ __launch_bounds__(256, 2)
void flash_kernel(const u16* __restrict__ qh, const u16* __restrict__ ql,
                  const u16* __restrict__ kh, const u16* __restrict__ vh,
                  float* __restrict__ X) {
    extern __shared__ __align__(16) char sm[];
    const uint32_t sbase = (uint32_t)__cvta_generic_to_shared(sm);
    const int n0 = blockIdx.x * 128;
    const int bh = blockIdx.y;
    const int b = bh >> 2, h = bh & 3;
    const int t = threadIdx.x;
    const int w = t >> 5, l = t & 31;
    const int g = l >> 2, tt = l & 3;
    const uint32_t ONES = 0x3C003C00u;

    const int km = t >> 1, khalf = (t & 1) * 32;
    const int vd = t >> 2, vm0 = (t & 3) * 32;
    const uint32_t kso = (uint32_t)(km * KPITCH + khalf * 2);
    const uint32_t vso = (uint32_t)(vd * VPITCH + vm0 * 2);
    const u16* kg = kh + ((size_t)bh*SEQ + km) * HD + khalf;
    const u16* vg = vh + ((size_t)bh*HD + vd) * SEQ + vm0;

    const uint32_t kfb = (uint32_t)((l & 7) * KPITCH + 16 * (l >> 3));
    const uint32_t vfb = (uint32_t)(((l & 7) + 8*(l >> 4)) * VPITCH + 16 * ((l >> 3) & 1));

    {
        const u16* qgh = qh + ((size_t)bh*SEQ + n0 + km) * HD + khalf;
        const u16* qgl = ql + ((size_t)bh*SEQ + n0 + km) * HD + khalf;
        #pragma unroll
        for (int u = 0; u < 4; u++) {
            cp16(sbase + QOFF + kso + 16*u,         qgh + 8*u);
            cp16(sbase + QOFF + 18432 + kso + 16*u, qgl + 8*u);
        }
        CP_COMMIT();
        #pragma unroll
        for (int u = 0; u < 4; u++) {
            cp16(sbase + kso + 16*u,         kg + 8*u);
            cp16(sbase + 18432 + vso + 16*u, vg + 8*u);
        }
        CP_COMMIT();
        #pragma unroll
        for (int u = 0; u < 4; u++) {
            cp16(sbase + STG + kso + 16*u,         kg + (size_t)128*HD + 8*u);
            cp16(sbase + STG + 18432 + vso + 16*u, vg + 128 + 8*u);
        }
        CP_COMMIT();
    }
    CP_WAIT(2);
    __syncthreads();
    uint32_t qa_h[4][4], qa_l[4][4];
    {
        const char* QH = sm + QOFF;
        const char* QL = sm + QOFF + 18432;
        const int r0 = (16*w + g) * KPITCH;
        #pragma unroll
        for (int j = 0; j < 4; j++) {
            const int c = (16*j + 2*tt) * 2;
            qa_h[j][0] = *(const uint32_t*)(QH + r0 + c);
            qa_h[j][1] = *(const uint32_t*)(QH + r0 + 8*KPITCH + c);
            qa_h[j][2] = *(const uint32_t*)(QH + r0 + c + 16);
            qa_h[j][3] = *(const uint32_t*)(QH + r0 + 8*KPITCH + c + 16);
            qa_l[j][0] = *(const uint32_t*)(QL + r0 + c);
            qa_l[j][1] = *(const uint32_t*)(QL + r0 + 8*KPITCH + c);
            qa_l[j][2] = *(const uint32_t*)(QL + r0 + c + 16);
            qa_l[j][3] = *(const uint32_t*)(QL + r0 + 8*KPITCH + c + 16);
        }
    }

    float O[8][4];
    #pragma unroll
    for (int i = 0; i < 8; i++) { O[i][0]=0.f; O[i][1]=0.f; O[i][2]=0.f; O[i][3]=0.f; }
    float lsacc[4] = {0.f, 0.f, 0.f, 0.f};
    uint32_t phi[8][2];

    for (int it = 0; it < 16; it++) {
        if (it < 15) { CP_WAIT(1); } else { CP_WAIT(0); }
        __syncthreads();
        const uint32_t kb = sbase + (it & 1) * STG + kfb;
        const uint32_t vb = sbase + (it & 1) * STG + 18432 + vfb;

        #pragma unroll
        for (int half = 0; half < 2; half++) {
            #pragma unroll
            for (int mc = 0; mc < 8; mc++) {
                float sa[4] = {0.f,0.f,0.f,0.f};
                float sb[4] = {0.f,0.f,0.f,0.f};
                const uint32_t rbase = (uint32_t)((64*half + 8*mc) * KPITCH);
                uint32_t bh_[8];
                ldsm4(kb + rbase,      bh_[0], bh_[1], bh_[2], bh_[3]);
                ldsm4(kb + rbase + 64, bh_[4], bh_[5], bh_[6], bh_[7]);
                #pragma unroll
                for (int j = 0; j < 4; j++) {
                    mma16816h(sa, qa_h[j], bh_[2*j], bh_[2*j+1]);
                    mma16816h(sb, qa_l[j], bh_[2*j], bh_[2*j+1]);
                }
                float p0 = ex2f(sa[0] + sb[0]);
                float p1 = ex2f(sa[1] + sb[1]);
                float p2 = ex2f(sa[2] + sb[2]);
                float p3 = ex2f(sa[3] + sb[3]);
                phi[mc][0] = packh2(p0, p1);
                phi[mc][1] = packh2(p2, p3);
            }
            #pragma unroll
            for (int jj = 0; jj < 4; jj++) {
                uint32_t ah[4] = { phi[2*jj][0], phi[2*jj][1], phi[2*jj+1][0], phi[2*jj+1][1] };
                mma16816h(lsacc, ah, ONES, ONES);
                const uint32_t vcol = (uint32_t)(128*half + 32*jj);
                #pragma unroll
                for (int dcp = 0; dcp < 4; dcp++) {
                    uint32_t h0,h1,h2,h3;
                    ldsm4(vb + dcp*(16*VPITCH) + vcol, h0, h1, h2, h3);
                    mma16816h(O[2*dcp],   ah, h0, h1);
                    mma16816h(O[2*dcp+1], ah, h2, h3);
                }
            }
        }
        __syncthreads();
        if (it < 14) {
            const u16* pk = kg + (size_t)(it + 2) * 128 * HD;
            const u16* pv = vg + (size_t)(it + 2) * 128;
            const uint32_t dk = sbase + (it & 1) * STG + kso;
            const uint32_t dv = sbase + (it & 1) * STG + 18432 + vso;
            #pragma unroll
            for (int u = 0; u < 4; u++) {
                cp16(dk + 16*u, pk + 8*u);
                cp16(dv + 16*u, pv + 8*u);
            }
            CP_COMMIT();
        }
    }

    const float i0 = 1.f / lsacc[0], i1 = 1.f / lsacc[2];
    #pragma unroll
    for (int dc = 0; dc < 8; dc++) {
        const int d0 = 8*dc + 2*tt;
        float* xp = X + ((size_t)b*DM + 4*d0 + h) * SEQ + n0 + 16*w;
        xp[g]             = O[dc][0] * i0;
        xp[4*SEQ + g]     = O[dc][1] * i0;
        xp[g + 8]         = O[dc][2] * i1;
        xp[4*SEQ + g + 8] = O[dc][3] * i1;
    }
}

// ---------------------------------------------------------------------------
extern "C" void kernel_launch(void* const* d_in, const int* in_sizes, int n_in,
                              void* d_out, int out_size) {
    const float* query = (const float*)d_in[0];
    const float* key   = (const float*)d_in[1];
    const float* value = (const float*)d_in[2];
    const float* Wq = (const float*)d_in[3];
    const float* bq = (const float*)d_in[4];
    const float* Wk = (const float*)d_in[5];
    const float* bk = (const float*)d_in[6];
    const float* Wv = (const float*)d_in[7];
    const float* bv = (const float*)d_in[8];
    const float* Wm = (const float*)d_in[9];
    const float* bm = (const float*)d_in[10];

    u16 *qh, *ql, *kh, *vh, *wh, *wl;
    float *x;
    cudaGetSymbolAddress((void**)&qh, g_qh);
    cudaGetSymbolAddress((void**)&ql, g_ql);
    cudaGetSymbolAddress((void**)&kh, g_kh);
    cudaGetSymbolAddress((void**)&vh, g_vh);
    cudaGetSymbolAddress((void**)&wh, g_wh);
    cudaGetSymbolAddress((void**)&wl, g_wl);
    cudaGetSymbolAddress((void**)&x,  g_x);

    cudaFuncSetAttribute(flash_kernel, cudaFuncAttributeMaxDynamicSharedMemorySize, FLASH_SMEM);
    cudaFuncSetAttribute(proj_tc<0>, cudaFuncAttributeMaxDynamicSharedMemorySize, PSM_BYTES);
    cudaFuncSetAttribute(proj_tc<1>, cudaFuncAttributeMaxDynamicSharedMemorySize, PSM_BYTES);
    cudaFuncSetAttribute(proj_tc<2>, cudaFuncAttributeMaxDynamicSharedMemorySize, PSM_BYTES);
    cudaFuncSetAttribute(proj_tc<3>, cudaFuncAttributeMaxDynamicSharedMemorySize, PSM_BYTES);

    wsplit_kernel<<<dim3(32, 4), 256>>>(Wq, Wk, Wv, Wm, wh, wl);

    dim3 pjGrid(SEQ/128, DM/128, BATCH);
    proj_tc<1><<<pjGrid, 256, PSM_BYTES>>>(wh,           wl,           bq, query, nullptr, qh, ql);
    proj_tc<3><<<pjGrid, 256, PSM_BYTES>>>(wh + DM*DM,   wl + DM*DM,   bk, key,   nullptr, kh, nullptr);
    proj_tc<2><<<pjGrid, 256, PSM_BYTES>>>(wh + 2*DM*DM, wl + 2*DM*DM, bv, value, nullptr, vh, nullptr);

    flash_kernel<<<dim3(SEQ/128, BH), 256, FLASH_SMEM>>>(qh, ql, kh, vh, x);

    proj_tc<0><<<pjGrid, 256, PSM_BYTES>>>(wh + 3*DM*DM, wl + 3*DM*DM, bm, x, (float*)d_out, nullptr, nullptr);
}

// round 16
// speedup vs baseline: 1.1066x; 1.1066x over previous
#include <cuda_runtime.h>
#include <cuda_bf16.h>
#include <cuda_fp16.h>
#include <cstdint>

#define BATCH 8
#define DM 256
#define NH 4
#define HD 64
#define SEQ 2048
#define BH (BATCH*NH)

typedef unsigned short u16;

// Q: [bh][n][d] fp16 hi/lo (pre-scaled by 0.125*log2e) ; K: [bh][m][d] fp16 ; V: [bh][d][m] fp16
__device__ u16  g_qh[(size_t)BH*SEQ*HD];
__device__ u16  g_ql[(size_t)BH*SEQ*HD];
__device__ u16  g_kh[(size_t)BH*SEQ*HD];
__device__ u16  g_vh[(size_t)BH*HD*SEQ];
__device__ float g_x [(size_t)BATCH*DM*SEQ];
// pre-split weights: [mat][o][i] fp16 hi/lo
__device__ u16  g_wh[4*DM*DM];
__device__ u16  g_wl[4*DM*DM];

#define QSCALE 0.18033688011112042f   // 0.125 * log2(e)

__device__ __forceinline__ float ex2f(float x) {
    float r; asm("ex2.approx.f32 %0, %1;" : "=f"(r) : "f"(x)); return r;
}
__device__ __forceinline__ uint32_t packh2(float lo, float hi) {
    uint32_t r; asm("cvt.rn.f16x2.f32 %0, %1, %2;" : "=r"(r) : "f"(hi), "f"(lo)); return r;
}
__device__ __forceinline__ void splithalf(float v, u16& h, u16& l) {
    __half hb = __float2half_rn(v);
    __half lb = __float2half_rn(v - __half2float(hb));
    h = __half_as_ushort(hb); l = __half_as_ushort(lb);
}
__device__ __forceinline__ void mma16816h(float* d, const uint32_t* a, uint32_t b0, uint32_t b1) {
    asm volatile("mma.sync.aligned.m16n8k16.row.col.f32.f16.f16.f32 "
                 "{%0,%1,%2,%3}, {%4,%5,%6,%7}, {%8,%9}, {%0,%1,%2,%3};\n"
                 : "+f"(d[0]), "+f"(d[1]), "+f"(d[2]), "+f"(d[3])
                 : "r"(a[0]), "r"(a[1]), "r"(a[2]), "r"(a[3]), "r"(b0), "r"(b1));
}
// fp16-accumulate variant (D/C = 2x f16x2)
__device__ __forceinline__ void mma16816hh(uint32_t* d, const uint32_t* a, uint32_t b0, uint32_t b1) {
    asm volatile("mma.sync.aligned.m16n8k16.row.col.f16.f16.f16.f16 "
                 "{%0,%1}, {%2,%3,%4,%5}, {%6,%7}, {%0,%1};\n"
                 : "+r"(d[0]), "+r"(d[1])
                 : "r"(a[0]), "r"(a[1]), "r"(a[2]), "r"(a[3]), "r"(b0), "r"(b1));
}
__device__ __forceinline__ void ldsm4(uint32_t a, uint32_t& r0, uint32_t& r1,
                                      uint32_t& r2, uint32_t& r3) {
    asm volatile("ldmatrix.sync.aligned.m8n8.x4.shared.b16 {%0,%1,%2,%3}, [%4];"
                 : "=r"(r0), "=r"(r1), "=r"(r2), "=r"(r3) : "r"(a));
}
__device__ __forceinline__ void ldsm4t(uint32_t a, uint32_t& r0, uint32_t& r1,
                                       uint32_t& r2, uint32_t& r3) {
    asm volatile("ldmatrix.sync.aligned.m8n8.x4.trans.shared.b16 {%0,%1,%2,%3}, [%4];"
                 : "=r"(r0), "=r"(r1), "=r"(r2), "=r"(r3) : "r"(a));
}
__device__ __forceinline__ void cp16(uint32_t saddr, const void* g) {
    asm volatile("cp.async.ca.shared.global [%0], [%1], 16;" :: "r"(saddr), "l"(g));
}
#define CP_COMMIT() asm volatile("cp.async.commit_group;" ::: "memory")
#define CP_WAIT(n)  asm volatile("cp.async.wait_group %0;" :: "n"(n) : "memory")

// ---------------------------------------------------------------------------
// One-shot weight splitter: 4 x [256][256] fp32 -> fp16 hi/lo. Grid (32, 4).
// ---------------------------------------------------------------------------
__global__ __launch_bounds__(256)
void wsplit_kernel(const float* __restrict__ W0, const float* __restrict__ W1,
                   const float* __restrict__ W2, const float* __restrict__ W3,
                   u16* __restrict__ Wh, u16* __restrict__ Wl) {
    const int mat = blockIdx.y;
    const float* src = (mat == 0) ? W0 : (mat == 1) ? W1 : (mat == 2) ? W2 : W3;
    const size_t base = (size_t)mat * DM * DM;
    const int i0 = (blockIdx.x * 256 + threadIdx.x) * 8;
    u16 h8[8], l8[8];
    #pragma unroll
    for (int p = 0; p < 8; p++)
        splithalf(src[i0 + p], h8[p], l8[p]);
    *(uint4*)&Wh[base + i0] = *(uint4*)h8;
    *(uint4*)&Wl[base + i0] = *(uint4*)l8;
}

// ---------------------------------------------------------------------------
// Tensor-core projection (R13 best, unchanged): fp16 2-term W, X fp16 hi.
// Tile 128o x 128n (256 CTAs = one wave at 2 CTAs/SM). K chunks of 32.
// MODE 0: fp32 [b][o][n]; MODE 1: fp16 hi/lo [bh][n][d], pre-scaled (Q);
// MODE 3: fp16 hi [bh][n][d] (K); MODE 2: fp16 hi [bh][d][m] (V).
// Grid (SEQ/128, DM/128, BATCH). 256 threads.
// ---------------------------------------------------------------------------
#define PJ_W 10240
#define PJ_X 8704
#define PJSTG (2*PJ_W + PJ_X)
#define PJ_WH(s) ((s)*PJSTG)
#define PJ_WL(s) ((s)*PJSTG + PJ_W)
#define PJ_XH(s) ((s)*PJSTG + 2*PJ_W)
#define PSM_BYTES 69632

template<int MODE>
__global__ __launch_bounds__(256, 2)
void proj_tc(const u16* __restrict__ Wh, const u16* __restrict__ Wl,
             const float* __restrict__ bias,
             const float* __restrict__ X, float* __restrict__ C0,
             u16* __restrict__ Ch, u16* __restrict__ Cl) {
    extern __shared__ __align__(16) char psm[];
    __shared__ float biasSm[128];
    const uint32_t sbase = (uint32_t)__cvta_generic_to_shared(psm);
    const int n0 = blockIdx.x * 128, o0 = blockIdx.y * 128, b = blockIdx.z;
    const int tid = threadIdx.x;
    const int w = tid >> 5, l = tid & 31;
    const int g = l >> 2, tt = l & 3;
    if (tid < 128) biasSm[tid] = bias[o0 + tid];

    float O[16][4];
    #pragma unroll
    for (int i = 0; i < 16; i++) { O[i][0]=0.f; O[i][1]=0.f; O[i][2]=0.f; O[i][3]=0.f; }

    const uint32_t xoff = (uint32_t)((8*((l >> 3) & 1) + (l & 7)) * 272 + 16 * (l >> 4));
    const int wrow = tid >> 1, wpc = tid & 1;
    const int xrow = tid >> 3, xn16 = (tid & 7) * 16;

    const u16* wsH = Wh + (size_t)(o0 + wrow) * DM + wpc * 16;
    const u16* wsL = Wl + (size_t)(o0 + wrow) * DM + wpc * 16;
    const float* xsrc = X + ((size_t)b * DM + xrow) * SEQ + n0 + xn16;
    const uint32_t wdh = sbase + wrow * 80 + wpc * 32;

    float4 rx0, rx1, rx2, rx3;

    #define PJ_WCP(c, s) do { \
        cp16(wdh + PJ_WH(s),      wsH + (c)*32); \
        cp16(wdh + PJ_WH(s) + 16, wsH + (c)*32 + 8); \
        cp16(wdh + PJ_WL(s),      wsL + (c)*32); \
        cp16(wdh + PJ_WL(s) + 16, wsL + (c)*32 + 8); \
        CP_COMMIT(); \
    } while (0)
    #define PJ_XFETCH(c) do { \
        const float* xp_ = xsrc + (size_t)((c)*32) * SEQ; \
        rx0 = *(const float4*)(xp_);      rx1 = *(const float4*)(xp_ + 4); \
        rx2 = *(const float4*)(xp_ + 8);  rx3 = *(const float4*)(xp_ + 12); \
    } while (0)
    #define PJ_XSTORE(s) do { \
        uint32_t a0 = packh2(rx0.x, rx0.y), a1 = packh2(rx0.z, rx0.w); \
        uint32_t a2 = packh2(rx1.x, rx1.y), a3 = packh2(rx1.z, rx1.w); \
        uint32_t a4 = packh2(rx2.x, rx2.y), a5 = packh2(rx2.z, rx2.w); \
        uint32_t a6 = packh2(rx3.x, rx3.y), a7 = packh2(rx3.z, rx3.w); \
        char* xd_ = psm + PJ_XH(s) + xrow*272 + xn16*2; \
        *(uint4*)(xd_)      = make_uint4(a0, a1, a2, a3); \
        *(uint4*)(xd_ + 16) = make_uint4(a4, a5, a6, a7); \
    } while (0)

    PJ_WCP(0, 0);
    PJ_XFETCH(0);
    PJ_XSTORE(0);
    CP_WAIT(0);
    __syncthreads();

    for (int c = 0; c < 8; c++) {
        const int cur = c & 1;
        if (c < 7) { PJ_WCP(c + 1, 1 - cur); PJ_XFETCH(c + 1); }
        #pragma unroll
        for (int s = 0; s < 2; s++) {
            uint32_t ah[4], al[4];
            const char* wp = psm + PJ_WH(cur) + (w*16 + g)*80 + s*32 + tt*4;
            ah[0] = *(const uint32_t*)wp;
            ah[1] = *(const uint32_t*)(wp + 8*80);
            ah[2] = *(const uint32_t*)(wp + 16);
            ah[3] = *(const uint32_t*)(wp + 8*80 + 16);
            const char* wq = wp + PJ_W;
            al[0] = *(const uint32_t*)wq;
            al[1] = *(const uint32_t*)(wq + 8*80);
            al[2] = *(const uint32_t*)(wq + 16);
            al[3] = *(const uint32_t*)(wq + 8*80 + 16);
            const uint32_t xb = sbase + PJ_XH(cur) + s*4352 + xoff;
            #pragma unroll
            for (int nbp = 0; nbp < 8; nbp++) {
                uint32_t h0, h1, h2, h3;
                ldsm4t(xb + 32*nbp, h0, h1, h2, h3);
                mma16816h(O[2*nbp],   ah, h0, h1);
                mma16816h(O[2*nbp+1], ah, h2, h3);
                mma16816h(O[2*nbp],   al, h0, h1);
                mma16816h(O[2*nbp+1], al, h2, h3);
            }
        }
        if (c < 7) { PJ_XSTORE(1 - cur); CP_WAIT(0); }
        __syncthreads();
    }
    #undef PJ_WCP
    #undef PJ_XFETCH
    #undef PJ_XSTORE

    float* Osm = (float*)psm;
    {
        const int r = w*16 + g;
        #pragma unroll
        for (int nb = 0; nb < 16; nb++) {
            const int cc = nb*8 + 2*tt;
            Osm[r*136 + cc]         = O[nb][0];
            Osm[r*136 + cc + 1]     = O[nb][1];
            Osm[(r+8)*136 + cc]     = O[nb][2];
            Osm[(r+8)*136 + cc + 1] = O[nb][3];
        }
    }
    __syncthreads();

    if (MODE == 0) {
        const int o = tid >> 1, half = (tid & 1) * 64;
        const float bi = biasSm[o];
        const float* src = Osm + o*136 + half;
        float* dst = C0 + ((size_t)b * DM + o0 + o) * SEQ + n0 + half;
        #pragma unroll
        for (int j = 0; j < 16; j++) {
            float4 v = *(const float4*)(src + 4*j);
            v.x += bi; v.y += bi; v.z += bi; v.w += bi;
            *(float4*)(dst + 4*j) = v;
        }
    } else if (MODE == 1) {
        #pragma unroll
        for (int r = 0; r < 2; r++) {
            const int task = tid + 256*r;
            const int n = task >> 2, hh = task & 3;
            u16 oh[32], ol[32];
            #pragma unroll
            for (int d = 0; d < 32; d++)
                splithalf((Osm[(4*d + hh)*136 + n] + biasSm[4*d + hh]) * QSCALE, oh[d], ol[d]);
            size_t dst = ((size_t)(b*NH + hh) * SEQ + n0 + n) * HD + (o0 >> 2);
            #pragma unroll
            for (int j = 0; j < 4; j++) {
                *(uint4*)(Ch + dst + 8*j) = *(uint4*)(oh + 8*j);
                *(uint4*)(Cl + dst + 8*j) = *(uint4*)(ol + 8*j);
            }
        }
    } else if (MODE == 3) {
        #pragma unroll
        for (int r = 0; r < 2; r++) {
            const int task = tid + 256*r;
            const int n = task >> 2, hh = task & 3;
            u16 oh[32];
            #pragma unroll
            for (int d = 0; d < 32; d++)
                oh[d] = __half_as_ushort(__float2half_rn(Osm[(4*d + hh)*136 + n] + biasSm[4*d + hh]));
            size_t dst = ((size_t)(b*NH + hh) * SEQ + n0 + n) * HD + (o0 >> 2);
            #pragma unroll
            for (int j = 0; j < 4; j++)
                *(uint4*)(Ch + dst + 8*j) = *(uint4*)(oh + 8*j);
        }
    } else {
        const int o = tid >> 1, mh = (tid & 1) * 64;
        const int chn = o0 + o;
        const int d = chn >> 2, hh = chn & 3;
        const float bi = biasSm[o];
        const float* src = Osm + o*136 + mh;
        u16 xh[64];
        #pragma unroll
        for (int j = 0; j < 64; j++)
            xh[j] = __half_as_ushort(__float2half_rn(src[j] + bi));
        size_t dst = ((size_t)(b*NH + hh) * HD + d) * SEQ + n0 + mh;
        #pragma unroll
        for (int j = 0; j < 8; j++)
            *(uint4*)(Ch + dst + 8*j) = *(uint4*)(xh + 8*j);
    }
}

// ---------------------------------------------------------------------------
// Fused flash attention: R13 structure, ONE change: q_lo S-term uses fp16
// accumulators (half-cost HMMA; term magnitude ~2^-8, f16 precision ample).
// Double-buffered cp.async. 2 CTAs/SM. 256 threads. Grid (SEQ/128, BH).
// ---------------------------------------------------------------------------
#define KPITCH 144
#define VPITCH 272
#define STG 35840
#define QOFF 71680
#define FLASH_SMEM 108544

__global__ __launch_bounds__(256, 2)
void flash_kernel(const u16* __restrict__ qh, const u16* __restrict__ ql,
                  const u16* __restrict__ kh, const u16* __restrict__ vh,
                  float* __restrict__ X) {
    extern __shared__ __align__(16) char sm[];
    const uint32_t sbase = (uint32_t)__cvta_generic_to_shared(sm);
    const int n0 = blockIdx.x * 128;
    const int bh = blockIdx.y;
    const int b = bh >> 2, h = bh & 3;
    const int t = threadIdx.x;
    const int w = t >> 5, l = t & 31;
    const int g = l >> 2, tt = l & 3;
    const uint32_t ONES = 0x3C003C00u;

    const int km = t >> 1, khalf = (t & 1) * 32;
    const int vd = t >> 2, vm0 = (t & 3) * 32;
    const uint32_t kso = (uint32_t)(km * KPITCH + khalf * 2);
    const uint32_t vso = (uint32_t)(vd * VPITCH + vm0 * 2);
    const u16* kg = kh + ((size_t)bh*SEQ + km) * HD + khalf;
    const u16* vg = vh + ((size_t)bh*HD + vd) * SEQ + vm0;

    const uint32_t kfb = (uint32_t)((l & 7) * KPITCH + 16 * (l >> 3));
    const uint32_t vfb = (uint32_t)(((l & 7) + 8*(l >> 4)) * VPITCH + 16 * ((l >> 3) & 1));

    {
        const u16* qgh = qh + ((size_t)bh*SEQ + n0 + km) * HD + khalf;
        const u16* qgl = ql + ((size_t)bh*SEQ + n0 + km) * HD + khalf;
        #pragma unroll
        for (int u = 0; u < 4; u++) {
            cp16(sbase + QOFF + kso + 16*u,         qgh + 8*u);
            cp16(sbase + QOFF + 18432 + kso + 16*u, qgl + 8*u);
        }
        CP_COMMIT();
        #pragma unroll
        for (int u = 0; u < 4; u++) {
            cp16(sbase + kso + 16*u,         kg + 8*u);
            cp16(sbase + 18432 + vso + 16*u, vg + 8*u);
        }
        CP_COMMIT();
        #pragma unroll
        for (int u = 0; u < 4; u++) {
            cp16(sbase + STG + kso + 16*u,         kg + (size_t)128*HD + 8*u);
            cp16(sbase + STG + 18432 + vso + 16*u, vg + 128 + 8*u);
        }
        CP_COMMIT();
    }
    CP_WAIT(2);
    __syncthreads();
    uint32_t qa_h[4][4], qa_l[4][4];
    {
        const char* QH = sm + QOFF;
        const char* QL = sm + QOFF + 18432;
        const int r0 = (16*w + g) * KPITCH;
        #pragma unroll
        for (int j = 0; j < 4; j++) {
            const int c = (16*j + 2*tt) * 2;
            qa_h[j][0] = *(const uint32_t*)(QH + r0 + c);
            qa_h[j][1] = *(const uint32_t*)(QH + r0 + 8*KPITCH + c);
            qa_h[j][2] = *(const uint32_t*)(QH + r0 + c + 16);
            qa_h[j][3] = *(const uint32_t*)(QH + r0 + 8*KPITCH + c + 16);
            qa_l[j][0] = *(const uint32_t*)(QL + r0 + c);
            qa_l[j][1] = *(const uint32_t*)(QL + r0 + 8*KPITCH + c);
            qa_l[j][2] = *(const uint32_t*)(QL + r0 + c + 16);
            qa_l[j][3] = *(const uint32_t*)(QL + r0 + 8*KPITCH + c + 16);
        }
    }

    float O[8][4];
    #pragma unroll
    for (int i = 0; i < 8; i++) { O[i][0]=0.f; O[i][1]=0.f; O[i][2]=0.f; O[i][3]=0.f; }
    float lsacc[4] = {0.f, 0.f, 0.f, 0.f};
    uint32_t phi[8][2];

    for (int it = 0; it < 16; it++) {
        if (it < 15) { CP_WAIT(1); } else { CP_WAIT(0); }
        __syncthreads();
        const uint32_t kb = sbase + (it & 1) * STG + kfb;
        const uint32_t vb = sbase + (it & 1) * STG + 18432 + vfb;

        #pragma unroll
        for (int half = 0; half < 2; half++) {
            // ---- S = q_hi*k (f32 accum) + q_lo*k (f16 accum) -> P
            #pragma unroll
            for (int mc = 0; mc < 8; mc++) {
                float sa[4] = {0.f,0.f,0.f,0.f};
                uint32_t sbh[2] = {0u, 0u};
                const uint32_t rbase = (uint32_t)((64*half + 8*mc) * KPITCH);
                uint32_t bh_[8];
                ldsm4(kb + rbase,      bh_[0], bh_[1], bh_[2], bh_[3]);
                ldsm4(kb + rbase + 64, bh_[4], bh_[5], bh_[6], bh_[7]);
                #pragma unroll
                for (int j = 0; j < 4; j++) {
                    mma16816h(sa, qa_h[j], bh_[2*j], bh_[2*j+1]);
                    mma16816hh(sbh, qa_l[j], bh_[2*j], bh_[2*j+1]);
                }
                float2 v01 = __half22float2(*(__half2*)&sbh[0]);
                float2 v23 = __half22float2(*(__half2*)&sbh[1]);
                float p0 = ex2f(sa[0] + v01.x);
                float p1 = ex2f(sa[1] + v01.y);
                float p2 = ex2f(sa[2] + v23.x);
                float p3 = ex2f(sa[3] + v23.y);
                phi[mc][0] = packh2(p0, p1);
                phi[mc][1] = packh2(p2, p3);
            }
            // ---- O += P * v ; ls += P * 1
            #pragma unroll
            for (int jj = 0; jj < 4; jj++) {
                uint32_t ah[4] = { phi[2*jj][0], phi[2*jj][1], phi[2*jj+1][0], phi[2*jj+1][1] };
                mma16816h(lsacc, ah, ONES, ONES);
                const uint32_t vcol = (uint32_t)(128*half + 32*jj);
                #pragma unroll
                for (int dcp = 0; dcp < 4; dcp++) {
                    uint32_t h0,h1,h2,h3;
                    ldsm4(vb + dcp*(16*VPITCH) + vcol, h0, h1, h2, h3);
                    mma16816h(O[2*dcp],   ah, h0, h1);
                    mma16816h(O[2*dcp+1], ah, h2, h3);
                }
            }
        }
        __syncthreads();
        if (it < 14) {
            const u16* pk = kg + (size_t)(it + 2) * 128 * HD;
            const u16* pv = vg + (size_t)(it + 2) * 128;
            const uint32_t dk = sbase + (it & 1) * STG + kso;
            const uint32_t dv = sbase + (it & 1) * STG + 18432 + vso;
            #pragma unroll
            for (int u = 0; u < 4; u++) {
                cp16(dk + 16*u, pk + 8*u);
                cp16(dv + 16*u, pv + 8*u);
            }
            CP_COMMIT();
        }
    }

    const float i0 = 1.f / lsacc[0], i1 = 1.f / lsacc[2];
    #pragma unroll
    for (int dc = 0; dc < 8; dc++) {
        const int d0 = 8*dc + 2*tt;
        float* xp = X + ((size_t)b*DM + 4*d0 + h) * SEQ + n0 + 16*w;
        xp[g]             = O[dc][0] * i0;
        xp[4*SEQ + g]     = O[dc][1] * i0;
        xp[g + 8]         = O[dc][2] * i1;
        xp[4*SEQ + g + 8] = O[dc][3] * i1;
    }
}

// ---------------------------------------------------------------------------
extern "C" void kernel_launch(void* const* d_in, const int* in_sizes, int n_in,
                              void* d_out, int out_size) {
    const float* query = (const float*)d_in[0];
    const float* key   = (const float*)d_in[1];
    const float* value = (const float*)d_in[2];
    const float* Wq = (const float*)d_in[3];
    const float* bq = (const float*)d_in[4];
    const float* Wk = (const float*)d_in[5];
    const float* bk = (const float*)d_in[6];
    const float* Wv = (const float*)d_in[7];
    const float* bv = (const float*)d_in[8];
    const float* Wm = (const float*)d_in[9];
    const float* bm = (const float*)d_in[10];

    u16 *qh, *ql, *kh, *vh, *wh, *wl;
    float *x;
    cudaGetSymbolAddress((void**)&qh, g_qh);
    cudaGetSymbolAddress((void**)&ql, g_ql);
    cudaGetSymbolAddress((void**)&kh, g_kh);
    cudaGetSymbolAddress((void**)&vh, g_vh);
    cudaGetSymbolAddress((void**)&wh, g_wh);
    cudaGetSymbolAddress((void**)&wl, g_wl);
    cudaGetSymbolAddress((void**)&x,  g_x);

    cudaFuncSetAttribute(flash_kernel, cudaFuncAttributeMaxDynamicSharedMemorySize, FLASH_SMEM);
    cudaFuncSetAttribute(proj_tc<0>, cudaFuncAttributeMaxDynamicSharedMemorySize, PSM_BYTES);
    cudaFuncSetAttribute(proj_tc<1>, cudaFuncAttributeMaxDynamicSharedMemorySize, PSM_BYTES);
    cudaFuncSetAttribute(proj_tc<2>, cudaFuncAttributeMaxDynamicSharedMemorySize, PSM_BYTES);
    cudaFuncSetAttribute(proj_tc<3>, cudaFuncAttributeMaxDynamicSharedMemorySize, PSM_BYTES);

    wsplit_kernel<<<dim3(32, 4), 256>>>(Wq, Wk, Wv, Wm, wh, wl);

    dim3 pjGrid(SEQ/128, DM/128, BATCH);
    proj_tc<1><<<pjGrid, 256, PSM_BYTES>>>(wh,           wl,           bq, query, nullptr, qh, ql);
    proj_tc<3><<<pjGrid, 256, PSM_BYTES>>>(wh + DM*DM,   wl + DM*DM,   bk, key,   nullptr, kh, nullptr);
    proj_tc<2><<<pjGrid, 256, PSM_BYTES>>>(wh + 2*DM*DM, wl + 2*DM*DM, bv, value, nullptr, vh, nullptr);

    flash_kernel<<<dim3(SEQ/128, BH), 256, FLASH_SMEM>>>(qh, ql, kh, vh, x);

    proj_tc<0><<<pjGrid, 256, PSM_BYTES>>>(wh + 3*DM*DM, wl + 3*DM*DM, bm, x, (float*)d_out, nullptr, nullptr);
}

// round 17
// speedup vs baseline: 1.3438x; 1.2143x over previous
#include <cuda_runtime.h>
#include <cuda_bf16.h>
#include <cuda_fp16.h>
#include <cstdint>

#define BATCH 8
#define DM 256
#define NH 4
#define HD 64
#define SEQ 2048
#define BH (BATCH*NH)

typedef unsigned short u16;

// Q: [bh][n][d] fp16 (pre-scaled by 0.125*log2e) ; K: [bh][m][d] fp16 ; V: [bh][d][m] fp16
__device__ u16  g_qh[(size_t)BH*SEQ*HD];
__device__ u16  g_kh[(size_t)BH*SEQ*HD];
__device__ u16  g_vh[(size_t)BH*HD*SEQ];
__device__ float g_x [(size_t)BATCH*DM*SEQ];
// pre-split weights: [mat][o][i] fp16 hi/lo
__device__ u16  g_wh[4*DM*DM];
__device__ u16  g_wl[4*DM*DM];

#define QSCALE 0.18033688011112042f   // 0.125 * log2(e)

__device__ __forceinline__ float ex2f(float x) {
    float r; asm("ex2.approx.f32 %0, %1;" : "=f"(r) : "f"(x)); return r;
}
__device__ __forceinline__ uint32_t packh2(float lo, float hi) {
    uint32_t r; asm("cvt.rn.f16x2.f32 %0, %1, %2;" : "=r"(r) : "f"(hi), "f"(lo)); return r;
}
__device__ __forceinline__ void splithalf(float v, u16& h, u16& l) {
    __half hb = __float2half_rn(v);
    __half lb = __float2half_rn(v - __half2float(hb));
    h = __half_as_ushort(hb); l = __half_as_ushort(lb);
}
__device__ __forceinline__ void mma16816h(float* d, const uint32_t* a, uint32_t b0, uint32_t b1) {
    asm volatile("mma.sync.aligned.m16n8k16.row.col.f32.f16.f16.f32 "
                 "{%0,%1,%2,%3}, {%4,%5,%6,%7}, {%8,%9}, {%0,%1,%2,%3};\n"
                 : "+f"(d[0]), "+f"(d[1]), "+f"(d[2]), "+f"(d[3])
                 : "r"(a[0]), "r"(a[1]), "r"(a[2]), "r"(a[3]), "r"(b0), "r"(b1));
}
__device__ __forceinline__ void ldsm4(uint32_t a, uint32_t& r0, uint32_t& r1,
                                      uint32_t& r2, uint32_t& r3) {
    asm volatile("ldmatrix.sync.aligned.m8n8.x4.shared.b16 {%0,%1,%2,%3}, [%4];"
                 : "=r"(r0), "=r"(r1), "=r"(r2), "=r"(r3) : "r"(a));
}
__device__ __forceinline__ void ldsm4t(uint32_t a, uint32_t& r0, uint32_t& r1,
                                       uint32_t& r2, uint32_t& r3) {
    asm volatile("ldmatrix.sync.aligned.m8n8.x4.trans.shared.b16 {%0,%1,%2,%3}, [%4];"
                 : "=r"(r0), "=r"(r1), "=r"(r2), "=r"(r3) : "r"(a));
}
__device__ __forceinline__ void cp16(uint32_t saddr, const void* g) {
    asm volatile("cp.async.ca.shared.global [%0], [%1], 16;" :: "r"(saddr), "l"(g));
}
#define CP_COMMIT() asm volatile("cp.async.commit_group;" ::: "memory")
#define CP_WAIT(n)  asm volatile("cp.async.wait_group %0;" :: "n"(n) : "memory")

// ---------------------------------------------------------------------------
// One-shot weight splitter: 4 x [256][256] fp32 -> fp16 hi/lo. Grid (32, 4).
// ---------------------------------------------------------------------------
__global__ __launch_bounds__(256)
void wsplit_kernel(const float* __restrict__ W0, const float* __restrict__ W1,
                   const float* __restrict__ W2, const float* __restrict__ W3,
                   u16* __restrict__ Wh, u16* __restrict__ Wl) {
    const int mat = blockIdx.y;
    const float* src = (mat == 0) ? W0 : (mat == 1) ? W1 : (mat == 2) ? W2 : W3;
    const size_t base = (size_t)mat * DM * DM;
    const int i0 = (blockIdx.x * 256 + threadIdx.x) * 8;
    u16 h8[8], l8[8];
    #pragma unroll
    for (int p = 0; p < 8; p++)
        splithalf(src[i0 + p], h8[p], l8[p]);
    *(uint4*)&Wh[base + i0] = *(uint4*)h8;
    *(uint4*)&Wl[base + i0] = *(uint4*)l8;
}

// ---------------------------------------------------------------------------
// Tensor-core projection (R13 structure): fp16 2-term W, X fp16 hi.
// Tile 128o x 128n (256 CTAs = one wave at 2 CTAs/SM). K chunks of 32.
// MODE 0: fp32 [b][o][n]; MODE 1: fp16 [bh][n][d] pre-scaled (Q);
// MODE 3: fp16 [bh][n][d] (K); MODE 2: fp16 [bh][d][m] (V).
// Grid (SEQ/128, DM/128, BATCH). 256 threads.
// ---------------------------------------------------------------------------
#define PJ_W 10240
#define PJ_X 8704
#define PJSTG (2*PJ_W + PJ_X)
#define PJ_WH(s) ((s)*PJSTG)
#define PJ_WL(s) ((s)*PJSTG + PJ_W)
#define PJ_XH(s) ((s)*PJSTG + 2*PJ_W)
#define PSM_BYTES 69632

template<int MODE>
__global__ __launch_bounds__(256, 2)
void proj_tc(const u16* __restrict__ Wh, const u16* __restrict__ Wl,
             const float* __restrict__ bias,
             const float* __restrict__ X, float* __restrict__ C0,
             u16* __restrict__ Ch) {
    extern __shared__ __align__(16) char psm[];
    __shared__ float biasSm[128];
    const uint32_t sbase = (uint32_t)__cvta_generic_to_shared(psm);
    const int n0 = blockIdx.x * 128, o0 = blockIdx.y * 128, b = blockIdx.z;
    const int tid = threadIdx.x;
    const int w = tid >> 5, l = tid & 31;
    const int g = l >> 2, tt = l & 3;
    if (tid < 128) biasSm[tid] = bias[o0 + tid];

    float O[16][4];
    #pragma unroll
    for (int i = 0; i < 16; i++) { O[i][0]=0.f; O[i][1]=0.f; O[i][2]=0.f; O[i][3]=0.f; }

    const uint32_t xoff = (uint32_t)((8*((l >> 3) & 1) + (l & 7)) * 272 + 16 * (l >> 4));
    const int wrow = tid >> 1, wpc = tid & 1;
    const int xrow = tid >> 3, xn16 = (tid & 7) * 16;

    const u16* wsH = Wh + (size_t)(o0 + wrow) * DM + wpc * 16;
    const u16* wsL = Wl + (size_t)(o0 + wrow) * DM + wpc * 16;
    const float* xsrc = X + ((size_t)b * DM + xrow) * SEQ + n0 + xn16;
    const uint32_t wdh = sbase + wrow * 80 + wpc * 32;

    float4 rx0, rx1, rx2, rx3;

    #define PJ_WCP(c, s) do { \
        cp16(wdh + PJ_WH(s),      wsH + (c)*32); \
        cp16(wdh + PJ_WH(s) + 16, wsH + (c)*32 + 8); \
        cp16(wdh + PJ_WL(s),      wsL + (c)*32); \
        cp16(wdh + PJ_WL(s) + 16, wsL + (c)*32 + 8); \
        CP_COMMIT(); \
    } while (0)
    #define PJ_XFETCH(c) do { \
        const float* xp_ = xsrc + (size_t)((c)*32) * SEQ; \
        rx0 = *(const float4*)(xp_);      rx1 = *(const float4*)(xp_ + 4); \
        rx2 = *(const float4*)(xp_ + 8);  rx3 = *(const float4*)(xp_ + 12); \
    } while (0)
    #define PJ_XSTORE(s) do { \
        uint32_t a0 = packh2(rx0.x, rx0.y), a1 = packh2(rx0.z, rx0.w); \
        uint32_t a2 = packh2(rx1.x, rx1.y), a3 = packh2(rx1.z, rx1.w); \
        uint32_t a4 = packh2(rx2.x, rx2.y), a5 = packh2(rx2.z, rx2.w); \
        uint32_t a6 = packh2(rx3.x, rx3.y), a7 = packh2(rx3.z, rx3.w); \
        char* xd_ = psm + PJ_XH(s) + xrow*272 + xn16*2; \
        *(uint4*)(xd_)      = make_uint4(a0, a1, a2, a3); \
        *(uint4*)(xd_ + 16) = make_uint4(a4, a5, a6, a7); \
    } while (0)

    PJ_WCP(0, 0);
    PJ_XFETCH(0);
    PJ_XSTORE(0);
    CP_WAIT(0);
    __syncthreads();

    for (int c = 0; c < 8; c++) {
        const int cur = c & 1;
        if (c < 7) { PJ_WCP(c + 1, 1 - cur); PJ_XFETCH(c + 1); }
        #pragma unroll
        for (int s = 0; s < 2; s++) {
            uint32_t ah[4], al[4];
            const char* wp = psm + PJ_WH(cur) + (w*16 + g)*80 + s*32 + tt*4;
            ah[0] = *(const uint32_t*)wp;
            ah[1] = *(const uint32_t*)(wp + 8*80);
            ah[2] = *(const uint32_t*)(wp + 16);
            ah[3] = *(const uint32_t*)(wp + 8*80 + 16);
            const char* wq = wp + PJ_W;
            al[0] = *(const uint32_t*)wq;
            al[1] = *(const uint32_t*)(wq + 8*80);
            al[2] = *(const uint32_t*)(wq + 16);
            al[3] = *(const uint32_t*)(wq + 8*80 + 16);
            const uint32_t xb = sbase + PJ_XH(cur) + s*4352 + xoff;
            #pragma unroll
            for (int nbp = 0; nbp < 8; nbp++) {
                uint32_t h0, h1, h2, h3;
                ldsm4t(xb + 32*nbp, h0, h1, h2, h3);
                mma16816h(O[2*nbp],   ah, h0, h1);
                mma16816h(O[2*nbp+1], ah, h2, h3);
                mma16816h(O[2*nbp],   al, h0, h1);
                mma16816h(O[2*nbp+1], al, h2, h3);
            }
        }
        if (c < 7) { PJ_XSTORE(1 - cur); CP_WAIT(0); }
        __syncthreads();
    }
    #undef PJ_WCP
    #undef PJ_XFETCH
    #undef PJ_XSTORE

    float* Osm = (float*)psm;
    {
        const int r = w*16 + g;
        #pragma unroll
        for (int nb = 0; nb < 16; nb++) {
            const int cc = nb*8 + 2*tt;
            Osm[r*136 + cc]         = O[nb][0];
            Osm[r*136 + cc + 1]     = O[nb][1];
            Osm[(r+8)*136 + cc]     = O[nb][2];
            Osm[(r+8)*136 + cc + 1] = O[nb][3];
        }
    }
    __syncthreads();

    if (MODE == 0) {
        const int o = tid >> 1, half = (tid & 1) * 64;
        const float bi = biasSm[o];
        const float* src = Osm + o*136 + half;
        float* dst = C0 + ((size_t)b * DM + o0 + o) * SEQ + n0 + half;
        #pragma unroll
        for (int j = 0; j < 16; j++) {
            float4 v = *(const float4*)(src + 4*j);
            v.x += bi; v.y += bi; v.z += bi; v.w += bi;
            *(float4*)(dst + 4*j) = v;
        }
    } else if (MODE == 1 || MODE == 3) {
        #pragma unroll
        for (int r = 0; r < 2; r++) {
            const int task = tid + 256*r;
            const int n = task >> 2, hh = task & 3;
            u16 oh[32];
            #pragma unroll
            for (int d = 0; d < 32; d++) {
                float v = Osm[(4*d + hh)*136 + n] + biasSm[4*d + hh];
                if (MODE == 1) v *= QSCALE;
                oh[d] = __half_as_ushort(__float2half_rn(v));
            }
            size_t dst = ((size_t)(b*NH + hh) * SEQ + n0 + n) * HD + (o0 >> 2);
            #pragma unroll
            for (int j = 0; j < 4; j++)
                *(uint4*)(Ch + dst + 8*j) = *(uint4*)(oh + 8*j);
        }
    } else {
        const int o = tid >> 1, mh = (tid & 1) * 64;
        const int chn = o0 + o;
        const int d = chn >> 2, hh = chn & 3;
        const float bi = biasSm[o];
        const float* src = Osm + o*136 + mh;
        u16 xh[64];
        #pragma unroll
        for (int j = 0; j < 64; j++)
            xh[j] = __half_as_ushort(__float2half_rn(src[j] + bi));
        size_t dst = ((size_t)(b*NH + hh) * HD + d) * SEQ + n0 + mh;
        #pragma unroll
        for (int j = 0; j < 8; j++)
            *(uint4*)(Ch + dst + 8*j) = *(uint4*)(xh + 8*j);
    }
}

// ---------------------------------------------------------------------------
// Fused flash attention: Q single fp16 (pre-scaled), K/V/P single-term,
// ls via all-ones MMA. 136 MMAs/tile (was 200). Double-buffered cp.async.
// 2 CTAs/SM. 256 threads. Grid (SEQ/128, BH). smem 88KB.
// ---------------------------------------------------------------------------
#define KPITCH 144
#define VPITCH 272
#define STG 35840            // K (18432) + V (17408) per stage
#define QOFF 71680           // Q fp16 at QOFF (18432)
#define FLASH_SMEM 90112

__global__ __launch_bounds__(256, 2)
void flash_kernel(const u16* __restrict__ qh, const u16* __restrict__ kh,
                  const u16* __restrict__ vh, float* __restrict__ X) {
    extern __shared__ __align__(16) char sm[];
    const uint32_t sbase = (uint32_t)__cvta_generic_to_shared(sm);
    const int n0 = blockIdx.x * 128;
    const int bh = blockIdx.y;
    const int b = bh >> 2, h = bh & 3;
    const int t = threadIdx.x;
    const int w = t >> 5, l = t & 31;
    const int g = l >> 2, tt = l & 3;
    const uint32_t ONES = 0x3C003C00u;

    const int km = t >> 1, khalf = (t & 1) * 32;
    const int vd = t >> 2, vm0 = (t & 3) * 32;
    const uint32_t kso = (uint32_t)(km * KPITCH + khalf * 2);
    const uint32_t vso = (uint32_t)(vd * VPITCH + vm0 * 2);
    const u16* kg = kh + ((size_t)bh*SEQ + km) * HD + khalf;
    const u16* vg = vh + ((size_t)bh*HD + vd) * SEQ + vm0;

    const uint32_t kfb = (uint32_t)((l & 7) * KPITCH + 16 * (l >> 3));
    const uint32_t vfb = (uint32_t)(((l & 7) + 8*(l >> 4)) * VPITCH + 16 * ((l >> 3) & 1));

    // ---- prologue: Q, then K0/V0, K1/V1
    {
        const u16* qg = qh + ((size_t)bh*SEQ + n0 + km) * HD + khalf;
        #pragma unroll
        for (int u = 0; u < 4; u++)
            cp16(sbase + QOFF + kso + 16*u, qg + 8*u);
        CP_COMMIT();
        #pragma unroll
        for (int u = 0; u < 4; u++) {
            cp16(sbase + kso + 16*u,         kg + 8*u);
            cp16(sbase + 18432 + vso + 16*u, vg + 8*u);
        }
        CP_COMMIT();
        #pragma unroll
        for (int u = 0; u < 4; u++) {
            cp16(sbase + STG + kso + 16*u,         kg + (size_t)128*HD + 8*u);
            cp16(sbase + STG + 18432 + vso + 16*u, vg + 128 + 8*u);
        }
        CP_COMMIT();
    }
    CP_WAIT(2);
    __syncthreads();
    uint32_t qa[4][4];
    {
        const char* QH = sm + QOFF;
        const int r0 = (16*w + g) * KPITCH;
        #pragma unroll
        for (int j = 0; j < 4; j++) {
            const int c = (16*j + 2*tt) * 2;
            qa[j][0] = *(const uint32_t*)(QH + r0 + c);
            qa[j][1] = *(const uint32_t*)(QH + r0 + 8*KPITCH + c);
            qa[j][2] = *(const uint32_t*)(QH + r0 + c + 16);
            qa[j][3] = *(const uint32_t*)(QH + r0 + 8*KPITCH + c + 16);
        }
    }

    float O[8][4];
    #pragma unroll
    for (int i = 0; i < 8; i++) { O[i][0]=0.f; O[i][1]=0.f; O[i][2]=0.f; O[i][3]=0.f; }
    float lsacc[4] = {0.f, 0.f, 0.f, 0.f};
    uint32_t phi[8][2];

    for (int it = 0; it < 16; it++) {
        if (it < 15) { CP_WAIT(1); } else { CP_WAIT(0); }
        __syncthreads();
        const uint32_t kb = sbase + (it & 1) * STG + kfb;
        const uint32_t vb = sbase + (it & 1) * STG + 18432 + vfb;

        #pragma unroll
        for (int half = 0; half < 2; half++) {
            // ---- S = q * k (single term, f32 accum) -> P
            #pragma unroll
            for (int mc = 0; mc < 8; mc++) {
                float sa[4] = {0.f,0.f,0.f,0.f};
                const uint32_t rbase = (uint32_t)((64*half + 8*mc) * KPITCH);
                uint32_t bh_[8];
                ldsm4(kb + rbase,      bh_[0], bh_[1], bh_[2], bh_[3]);
                ldsm4(kb + rbase + 64, bh_[4], bh_[5], bh_[6], bh_[7]);
                #pragma unroll
                for (int j = 0; j < 4; j++)
                    mma16816h(sa, qa[j], bh_[2*j], bh_[2*j+1]);
                float p0 = ex2f(sa[0]);
                float p1 = ex2f(sa[1]);
                float p2 = ex2f(sa[2]);
                float p3 = ex2f(sa[3]);
                phi[mc][0] = packh2(p0, p1);
                phi[mc][1] = packh2(p2, p3);
            }
            // ---- O += P * v ; ls += P * 1
            #pragma unroll
            for (int jj = 0; jj < 4; jj++) {
                uint32_t ah[4] = { phi[2*jj][0], phi[2*jj][1], phi[2*jj+1][0], phi[2*jj+1][1] };
                mma16816h(lsacc, ah, ONES, ONES);
                const uint32_t vcol = (uint32_t)(128*half + 32*jj);
                #pragma unroll
                for (int dcp = 0; dcp < 4; dcp++) {
                    uint32_t h0,h1,h2,h3;
                    ldsm4(vb + dcp*(16*VPITCH) + vcol, h0, h1, h2, h3);
                    mma16816h(O[2*dcp],   ah, h0, h1);
                    mma16816h(O[2*dcp+1], ah, h2, h3);
                }
            }
        }
        __syncthreads();
        if (it < 14) {
            const u16* pk = kg + (size_t)(it + 2) * 128 * HD;
            const u16* pv = vg + (size_t)(it + 2) * 128;
            const uint32_t dk = sbase + (it & 1) * STG + kso;
            const uint32_t dv = sbase + (it & 1) * STG + 18432 + vso;
            #pragma unroll
            for (int u = 0; u < 4; u++) {
                cp16(dk + 16*u, pk + 8*u);
                cp16(dv + 16*u, pv + 8*u);
            }
            CP_COMMIT();
        }
    }

    const float i0 = 1.f / lsacc[0], i1 = 1.f / lsacc[2];
    #pragma unroll
    for (int dc = 0; dc < 8; dc++) {
        const int d0 = 8*dc + 2*tt;
        float* xp = X + ((size_t)b*DM + 4*d0 + h) * SEQ + n0 + 16*w;
        xp[g]             = O[dc][0] * i0;
        xp[4*SEQ + g]     = O[dc][1] * i0;
        xp[g + 8]         = O[dc][2] * i1;
        xp[4*SEQ + g + 8] = O[dc][3] * i1;
    }
}

// ---------------------------------------------------------------------------
extern "C" void kernel_launch(void* const* d_in, const int* in_sizes, int n_in,
                              void* d_out, int out_size) {
    const float* query = (const float*)d_in[0];
    const float* key   = (const float*)d_in[1];
    const float* value = (const float*)d_in[2];
    const float* Wq = (const float*)d_in[3];
    const float* bq = (const float*)d_in[4];
    const float* Wk = (const float*)d_in[5];
    const float* bk = (const float*)d_in[6];
    const float* Wv = (const float*)d_in[7];
    const float* bv = (const float*)d_in[8];
    const float* Wm = (const float*)d_in[9];
    const float* bm = (const float*)d_in[10];

    u16 *qh, *kh, *vh, *wh, *wl;
    float *x;
    cudaGetSymbolAddress((void**)&qh, g_qh);
    cudaGetSymbolAddress((void**)&kh, g_kh);
    cudaGetSymbolAddress((void**)&vh, g_vh);
    cudaGetSymbolAddress((void**)&wh, g_wh);
    cudaGetSymbolAddress((void**)&wl, g_wl);
    cudaGetSymbolAddress((void**)&x,  g_x);

    cudaFuncSetAttribute(flash_kernel, cudaFuncAttributeMaxDynamicSharedMemorySize, FLASH_SMEM);
    cudaFuncSetAttribute(proj_tc<0>, cudaFuncAttributeMaxDynamicSharedMemorySize, PSM_BYTES);
    cudaFuncSetAttribute(proj_tc<1>, cudaFuncAttributeMaxDynamicSharedMemorySize, PSM_BYTES);
    cudaFuncSetAttribute(proj_tc<2>, cudaFuncAttributeMaxDynamicSharedMemorySize, PSM_BYTES);
    cudaFuncSetAttribute(proj_tc<3>, cudaFuncAttributeMaxDynamicSharedMemorySize, PSM_BYTES);

    wsplit_kernel<<<dim3(32, 4), 256>>>(Wq, Wk, Wv, Wm, wh, wl);

    dim3 pjGrid(SEQ/128, DM/128, BATCH);
    proj_tc<1><<<pjGrid, 256, PSM_BYTES>>>(wh,           wl,           bq, query, nullptr, qh);
    proj_tc<3><<<pjGrid, 256, PSM_BYTES>>>(wh + DM*DM,   wl + DM*DM,   bk, key,   nullptr, kh);
    proj_tc<2><<<pjGrid, 256, PSM_BYTES>>>(wh + 2*DM*DM, wl + 2*DM*DM, bv, value, nullptr, vh);

    flash_kernel<<<dim3(SEQ/128, BH), 256, FLASH_SMEM>>>(qh, kh, vh, x);

    proj_tc<0><<<pjGrid, 256, PSM_BYTES>>>(wh + 3*DM*DM, wl + 3*DM*DM, bm, x, (float*)d_out, nullptr);
}